// round 12
// baseline (speedup 1.0000x reference)
#include <cuda_runtime.h>

#define HH 1024
#define WW 1024
#define CC 8
#define NN 2
#define TH 32
#define TW 16
#define SROWS 64                 // TH + 32
#define SCOLS 48                 // TW + 32
#define SCH (SROWS*SCOLS)        // 3072
#define NTHR 256

// ---- device-global scratch / accumulators ----
__device__ __align__(16) float g_scratch[NN*HH*WW];
__device__ unsigned int g_minbits;
__device__ unsigned int g_maxbits;
__device__ double g_sum;
__device__ unsigned long long g_cnt;

__global__ void init_k() {
    g_minbits = 0x7F800000u;
    g_maxbits = 0u;
    g_sum = 0.0;
    g_cnt = 0ull;
}

// Pass 1: gray diff + global min/max
__global__ void __launch_bounds__(256) mask_k(const float* __restrict__ mso,
                                              const float* __restrict__ pan) {
    int t = blockIdx.x * 256 + threadIdx.x;
    int p = t << 2;
    int n = p >> 20;
    int hw = p & 0xFFFFF;

    float4 acc = make_float4(0.f, 0.f, 0.f, 0.f);
#pragma unroll
    for (int c = 0; c < CC; c++) {
        float4 v = *(const float4*)&mso[((size_t)(n * CC + c) << 20) + hw];
        acc.x += v.x; acc.y += v.y; acc.z += v.z; acc.w += v.w;
    }
    float4 pv = *(const float4*)&pan[((size_t)n << 20) + hw];
    float4 g;
    g.x = fabsf(acc.x * 0.125f - pv.x);
    g.y = fabsf(acc.y * 0.125f - pv.y);
    g.z = fabsf(acc.z * 0.125f - pv.z);
    g.w = fabsf(acc.w * 0.125f - pv.w);
    *(float4*)&g_scratch[p] = g;

    float lmin = fminf(fminf(g.x, g.y), fminf(g.z, g.w));
    float lmax = fmaxf(fmaxf(g.x, g.y), fmaxf(g.z, g.w));
#pragma unroll
    for (int o = 16; o; o >>= 1) {
        lmin = fminf(lmin, __shfl_xor_sync(0xffffffffu, lmin, o));
        lmax = fmaxf(lmax, __shfl_xor_sync(0xffffffffu, lmax, o));
    }
    __shared__ float smn[8], smx[8];
    int lane = threadIdx.x & 31, wid = threadIdx.x >> 5;
    if (!lane) { smn[wid] = lmin; smx[wid] = lmax; }
    __syncthreads();
    if (threadIdx.x == 0) {
        float mn = smn[0], mx = smx[0];
#pragma unroll
        for (int i = 1; i < 8; i++) { mn = fminf(mn, smn[i]); mx = fmaxf(mx, smx[i]); }
        atomicMin(&g_minbits, __float_as_uint(mn));
        atomicMax(&g_maxbits, __float_as_uint(mx));
    }
}

// One sliding-window step: target row (r0 + 4k) feeds px-row0 @ di=k and px-row1 @ di=k-1.
template<bool DO0, bool DO1>
__device__ __forceinline__ void sad_step(const float* __restrict__ sT, int rb,
                                         const float* __restrict__ m0r,
                                         const float* __restrict__ m1r,
                                         float& min0, float& min1) {
    float part0[9], part1[9];
#pragma unroll
    for (int c = 0; c < CC; c++) {
        const float* p = sT + c * SCH + rb;
        const float m0 = m0r[c];
        const float m1 = m1r[c];
#pragma unroll
        for (int dj = 0; dj < 9; dj++) {
            float tv = p[dj << 2];
            if (DO0) {
                float d = fabsf(m0 - tv);
                part0[dj] = (c == 0) ? d : part0[dj] + d;
            }
            if (DO1) {
                float d = fabsf(m1 - tv);
                part1[dj] = (c == 0) ? d : part1[dj] + d;
            }
        }
    }
#pragma unroll
    for (int dj = 0; dj < 9; dj++) {
        if (DO0) min0 = fminf(min0, part0[dj]);
        if (DO1) min1 = fminf(min1, part1[dj]);
    }
}

// Pass 2: min-shift SAD. 32x16 tile, 256 threads, 2 rows x 1 px per thread,
// 96KB smem -> 2 CTAs/SM so loads of one CTA overlap compute of the other.
__global__ void __launch_bounds__(NTHR, 2) main_k(const float* __restrict__ ms,
                                                  const float* __restrict__ tgt) {
    extern __shared__ float sT[];   // [CC][SROWS][SCOLS]

    const int n  = blockIdx.z;
    const int h0 = blockIdx.y * TH;
    const int w0 = blockIdx.x * TW;
    const int tx = threadIdx.x;      // 0..15 -> 1 px along w
    const int ty = threadIdx.y;      // 0..15 -> rows r0 and r0+4
    const int tid = ty * 16 + tx;

    // ---- load target tile (reflect pad), vectorized ----
    const int CPL4 = SCOLS / 4;                // 12 float4 per row
    const int NV4  = CC * SROWS * CPL4;        // 6144 = 24 * 256
#pragma unroll 4
    for (int it = 0; it < NV4 / NTHR; it++) {
        int e4  = it * NTHR + tid;
        int c   = e4 / (SROWS * CPL4);
        int rem = e4 - c * (SROWS * CPL4);
        int r   = rem / CPL4;
        int q   = rem - r * CPL4;
        int gr = h0 + r - 16;
        gr = gr < 0 ? -gr : (gr >= HH ? 2 * HH - 2 - gr : gr);
        const float* src = tgt + (((size_t)n * CC + c) * HH + gr) * WW;
        int gcb = w0 + q * 4 - 16;
        float4 v;
        if (gcb >= 0 && gcb + 4 <= WW) {
            v = *(const float4*)(src + gcb);
        } else {
            int g0 = gcb, g1 = gcb + 1, g2 = gcb + 2, g3 = gcb + 3;
            g0 = g0 < 0 ? -g0 : (g0 >= WW ? 2 * WW - 2 - g0 : g0);
            g1 = g1 < 0 ? -g1 : (g1 >= WW ? 2 * WW - 2 - g1 : g1);
            g2 = g2 < 0 ? -g2 : (g2 >= WW ? 2 * WW - 2 - g2 : g2);
            g3 = g3 < 0 ? -g3 : (g3 >= WW ? 2 * WW - 2 - g3 : g3);
            v = make_float4(src[g0], src[g1], src[g2], src[g3]);
        }
        *(float4*)&sT[c * SCH + r * SCOLS + q * 4] = v;
    }
    __syncthreads();

    // rows owned by this thread: r0 and r0+4 (disjoint cover of 0..31)
    const int r0 = (ty & 3) + ((ty >> 2) << 3);
    const int r1 = r0 + 4;
    const int w  = w0 + tx;

    // ms pixels: 8 channels x 1 px, two rows
    float m0r[CC], m1r[CC];
#pragma unroll
    for (int c = 0; c < CC; c++) {
        const float* base = &ms[(((size_t)n * CC + c) * HH + h0) * WW + w];
        m0r[c] = base[(size_t)r0 * WW];
        m1r[c] = base[(size_t)r1 * WW];
    }

    float min0 = 3.4e38f, min1 = 3.4e38f;
    const int rbase = r0 * SCOLS + tx;

    sad_step<true, false>(sT, rbase, m0r, m1r, min0, min1);              // k = 0
#pragma unroll 1
    for (int k = 1; k < 9; k++)
        sad_step<true, true>(sT, rbase + k * 4 * SCOLS, m0r, m1r, min0, min1);
    sad_step<false, true>(sT, rbase + 9 * 4 * SCOLS, m0r, m1r, min0, min1); // k = 9

    // ---- mask + reduction ----
    const float mn  = __uint_as_float(g_minbits);
    const float mx  = __uint_as_float(g_maxbits);
    const float thr = mn + (mx - mn) * (10.0f / 255.0f);

    const float* gbase = &g_scratch[((size_t)n << 20) + (size_t)h0 * WW + w];
    float g0 = gbase[(size_t)r0 * WW];
    float g1 = gbase[(size_t)r1 * WW];

    float lsum = 0.f;
    int   lcnt = 0;
    if (g0 > thr) { lsum += min0; lcnt++; }
    if (g1 > thr) { lsum += min1; lcnt++; }

#pragma unroll
    for (int o = 16; o; o >>= 1) {
        lsum += __shfl_xor_sync(0xffffffffu, lsum, o);
        lcnt += __shfl_xor_sync(0xffffffffu, lcnt, o);
    }
    __shared__ float wsum[8];
    __shared__ int   wcnt[8];
    int lane = tid & 31, wid = tid >> 5;
    if (!lane) { wsum[wid] = lsum; wcnt[wid] = lcnt; }
    __syncthreads();
    if (tid == 0) {
        double bs = 0.0; long long bc = 0;
#pragma unroll
        for (int i = 0; i < 8; i++) { bs += (double)wsum[i]; bc += wcnt[i]; }
        atomicAdd(&g_sum, bs);
        atomicAdd(&g_cnt, (unsigned long long)bc);
    }
}

__global__ void fin_k(float* out) {
    unsigned long long c = g_cnt;
    out[0] = (c > 0ull) ? (float)(g_sum / (double)c) : 0.0f;
}

extern "C" void kernel_launch(void* const* d_in, const int* in_sizes, int n_in,
                              void* d_out, int out_size) {
    const float* ms  = (const float*)d_in[0];
    const float* tgt = (const float*)d_in[1];
    const float* mso = (const float*)d_in[2];
    const float* pan = (const float*)d_in[3];
    float* out = (float*)d_out;

    const int smem = CC * SCH * (int)sizeof(float);   // 98304 B -> 2 CTAs/SM
    cudaFuncSetAttribute(main_k, cudaFuncAttributeMaxDynamicSharedMemorySize, smem);

    init_k<<<1, 1>>>();
    mask_k<<<(NN * HH * WW) / 4 / 256, 256>>>(mso, pan);
    dim3 grid(WW / TW, HH / TH, NN), blk(16, 16);
    main_k<<<grid, blk, smem>>>(ms, tgt);
    fin_k<<<1, 1>>>(out);
}

// round 13
// speedup vs baseline: 1.7139x; 1.7139x over previous
#include <cuda_runtime.h>

#define HH 1024
#define WW 1024
#define CC 8
#define NN 2
#define TH 32
#define TW 64
#define SROWS 64                 // TH + 32
#define SCOLS 96                 // TW + 32
#define SCH (SROWS*SCOLS)
#define NTHR 512

// ---- device-global scratch / accumulators ----
__device__ __align__(16) float g_scratch[NN*HH*WW];
__device__ unsigned int g_minbits;
__device__ unsigned int g_maxbits;
__device__ double g_sum;
__device__ unsigned long long g_cnt;

__global__ void init_k() {
    g_minbits = 0x7F800000u;
    g_maxbits = 0u;
    g_sum = 0.0;
    g_cnt = 0ull;
}

// Pass 1: gray diff + global min/max
__global__ void __launch_bounds__(256) mask_k(const float* __restrict__ mso,
                                              const float* __restrict__ pan) {
    int t = blockIdx.x * 256 + threadIdx.x;
    int p = t << 2;
    int n = p >> 20;
    int hw = p & 0xFFFFF;

    float4 acc = make_float4(0.f, 0.f, 0.f, 0.f);
#pragma unroll
    for (int c = 0; c < CC; c++) {
        float4 v = *(const float4*)&mso[((size_t)(n * CC + c) << 20) + hw];
        acc.x += v.x; acc.y += v.y; acc.z += v.z; acc.w += v.w;
    }
    float4 pv = *(const float4*)&pan[((size_t)n << 20) + hw];
    float4 g;
    g.x = fabsf(acc.x * 0.125f - pv.x);
    g.y = fabsf(acc.y * 0.125f - pv.y);
    g.z = fabsf(acc.z * 0.125f - pv.z);
    g.w = fabsf(acc.w * 0.125f - pv.w);
    *(float4*)&g_scratch[p] = g;

    float lmin = fminf(fminf(g.x, g.y), fminf(g.z, g.w));
    float lmax = fmaxf(fmaxf(g.x, g.y), fmaxf(g.z, g.w));
#pragma unroll
    for (int o = 16; o; o >>= 1) {
        lmin = fminf(lmin, __shfl_xor_sync(0xffffffffu, lmin, o));
        lmax = fmaxf(lmax, __shfl_xor_sync(0xffffffffu, lmax, o));
    }
    __shared__ float smn[8], smx[8];
    int lane = threadIdx.x & 31, wid = threadIdx.x >> 5;
    if (!lane) { smn[wid] = lmin; smx[wid] = lmax; }
    __syncthreads();
    if (threadIdx.x == 0) {
        float mn = smn[0], mx = smx[0];
#pragma unroll
        for (int i = 1; i < 8; i++) { mn = fminf(mn, smn[i]); mx = fmaxf(mx, smx[i]); }
        atomicMin(&g_minbits, __float_as_uint(mn));
        atomicMax(&g_maxbits, __float_as_uint(mx));
    }
}

__device__ __forceinline__ unsigned int smem_u32(const void* p) {
    unsigned int a;
    asm("{ .reg .u64 t; cvta.to.shared.u64 t, %1; cvt.u32.u64 %0, t; }"
        : "=r"(a) : "l"(p));
    return a;
}
__device__ __forceinline__ void mbar_init(unsigned int mbar, unsigned int cnt) {
    asm volatile("mbarrier.init.shared.b64 [%0], %1;" :: "r"(mbar), "r"(cnt) : "memory");
}
__device__ __forceinline__ void mbar_expect(unsigned int mbar, unsigned int bytes) {
    asm volatile("mbarrier.arrive.expect_tx.shared.b64 _, [%0], %1;"
                 :: "r"(mbar), "r"(bytes) : "memory");
}
__device__ __forceinline__ void bulk_cp(unsigned int dst, const void* src,
                                        unsigned int bytes, unsigned int mbar) {
    asm volatile("cp.async.bulk.shared::cta.global.mbarrier::complete_tx::bytes "
                 "[%0], [%1], %2, [%3];"
                 :: "r"(dst), "l"(src), "r"(bytes), "r"(mbar) : "memory");
}
__device__ __forceinline__ void mbar_wait(unsigned int mbar, unsigned int parity) {
    asm volatile(
        "{\n\t.reg .pred P;\n\t"
        "W%=:\n\t"
        "mbarrier.try_wait.parity.acquire.cta.shared::cta.b64 P, [%0], %1, 0x989680;\n\t"
        "@P bra.uni D%=;\n\t"
        "bra.uni W%=;\n\t"
        "D%=:\n\t}"
        :: "r"(mbar), "r"(parity) : "memory");
}

// One sliding-window step: target row (r0 + 4k) feeds px-row0 @ di=k and px-row1 @ di=k-1.
template<bool DO0, bool DO1>
__device__ __forceinline__ void sad_step(const float* __restrict__ sT, int rb,
                                         const float2* __restrict__ m0r,
                                         const float2* __restrict__ m1r,
                                         float* __restrict__ minv0,
                                         float* __restrict__ minv1) {
    float part0[18], part1[18];
#pragma unroll
    for (int c = 0; c < CC; c++) {
        const float* p = sT + c * SCH + rb;
        const float2 m0 = m0r[c];
        const float2 m1 = m1r[c];
#pragma unroll
        for (int dj = 0; dj < 9; dj++) {
            float2 tv = *(const float2*)(p + (dj << 2));
            if (DO0) {
                float dx = fabsf(m0.x - tv.x);
                float dy = fabsf(m0.y - tv.y);
                if (c == 0) { part0[dj*2+0] = dx; part0[dj*2+1] = dy; }
                else        { part0[dj*2+0] += dx; part0[dj*2+1] += dy; }
            }
            if (DO1) {
                float dx = fabsf(m1.x - tv.x);
                float dy = fabsf(m1.y - tv.y);
                if (c == 0) { part1[dj*2+0] = dx; part1[dj*2+1] = dy; }
                else        { part1[dj*2+0] += dx; part1[dj*2+1] += dy; }
            }
        }
    }
    if (DO0) {
#pragma unroll
        for (int dj = 0; dj < 9; dj++) {
            minv0[0] = fminf(minv0[0], part0[dj*2+0]);
            minv0[1] = fminf(minv0[1], part0[dj*2+1]);
        }
    }
    if (DO1) {
#pragma unroll
        for (int dj = 0; dj < 9; dj++) {
            minv1[0] = fminf(minv1[0], part1[dj*2+0]);
            minv1[1] = fminf(minv1[1], part1[dj*2+1]);
        }
    }
}

// Pass 2: min-shift SAD, 512 threads, 2 rows x 2 px/thread, async chunked tile load
__global__ void __launch_bounds__(NTHR, 1) main_k(const float* __restrict__ ms,
                                                  const float* __restrict__ tgt) {
    extern __shared__ float sT[];   // [CC][SROWS][SCOLS]
    __shared__ __align__(8) unsigned long long mbars[3];

    const int n  = blockIdx.z;
    const int h0 = blockIdx.y * TH;
    const int w0 = blockIdx.x * TW;
    const int tx = threadIdx.x;      // 0..31 -> 2 px along w
    const int ty = threadIdx.y;      // 0..15 -> rows r0 and r0+4
    const int tid = ty * 32 + tx;

    const bool interior = (blockIdx.x > 0) && (blockIdx.x < gridDim.x - 1);

    if (interior) {
        // ---- async bulk-copy tile load: one 384B row per thread, 3 chunks ----
        if (tid == 0) {
            unsigned int mb = smem_u32(mbars);
            mbar_init(mb,      1);
            mbar_init(mb +  8, 1);
            mbar_init(mb + 16, 1);
        }
        __syncthreads();
        if (tid == 0) {
            unsigned int mb = smem_u32(mbars);
            mbar_expect(mb,      28 * CC * SCOLS * 4);   // rows [0,28)
            mbar_expect(mb +  8, 16 * CC * SCOLS * 4);   // rows [28,44)
            mbar_expect(mb + 16, 20 * CC * SCOLS * 4);   // rows [44,64)
        }
        {
            const int c = tid >> 6;          // 0..7
            const int r = tid & 63;          // 0..63
            int gr = h0 + r - 16;
            gr = gr < 0 ? -gr : (gr >= HH ? 2 * HH - 2 - gr : gr);
            const float* src = tgt + (((size_t)n * CC + c) * HH + gr) * WW + (w0 - 16);
            unsigned int dst = smem_u32(sT + (c * SROWS + r) * SCOLS);
            unsigned int mb  = smem_u32(mbars) + ((r < 28) ? 0u : (r < 44) ? 8u : 16u);
            bulk_cp(dst, src, SCOLS * 4, mb);
        }
    } else {
        // ---- manual loader with column reflect (boundary blocks) ----
        const int CPL4 = SCOLS / 4;
        const int NV4  = CC * SROWS * CPL4;
#pragma unroll 4
        for (int it = 0; it < NV4 / NTHR; it++) {
            int e4  = it * NTHR + tid;
            int c   = e4 / (SROWS * CPL4);
            int rem = e4 - c * (SROWS * CPL4);
            int r   = rem / CPL4;
            int q   = rem - r * CPL4;
            int gr = h0 + r - 16;
            gr = gr < 0 ? -gr : (gr >= HH ? 2 * HH - 2 - gr : gr);
            const float* src = tgt + (((size_t)n * CC + c) * HH + gr) * WW;
            int gcb = w0 + q * 4 - 16;
            float4 v;
            if (gcb >= 0 && gcb + 4 <= WW) {
                v = *(const float4*)(src + gcb);
            } else {
                int g0 = gcb, g1 = gcb + 1, g2 = gcb + 2, g3 = gcb + 3;
                g0 = g0 < 0 ? -g0 : (g0 >= WW ? 2 * WW - 2 - g0 : g0);
                g1 = g1 < 0 ? -g1 : (g1 >= WW ? 2 * WW - 2 - g1 : g1);
                g2 = g2 < 0 ? -g2 : (g2 >= WW ? 2 * WW - 2 - g2 : g2);
                g3 = g3 < 0 ? -g3 : (g3 >= WW ? 2 * WW - 2 - g3 : g3);
                v = make_float4(src[g0], src[g1], src[g2], src[g3]);
            }
            *(float4*)&sT[c * SCH + r * SCOLS + q * 4] = v;
        }
        __syncthreads();
    }

    // rows owned by this thread: r0 and r0+4 (disjoint cover of 0..31)
    const int r0    = (ty & 3) + ((ty >> 2) << 3);
    const int r1    = r0 + 4;
    const int wbase = w0 + (tx << 1);

    // ms pixels (overlaps the async tile transfer)
    float2 m0r[CC], m1r[CC];
#pragma unroll
    for (int c = 0; c < CC; c++) {
        const float* base = &ms[(((size_t)n * CC + c) * HH + h0) * WW + wbase];
        m0r[c] = *(const float2*)(base + (size_t)r0 * WW);
        m1r[c] = *(const float2*)(base + (size_t)r1 * WW);
    }
    // mask values too
    const float* gbase = &g_scratch[((size_t)n << 20) + (size_t)h0 * WW + wbase];
    float2 ga = *(const float2*)(gbase + (size_t)r0 * WW);
    float2 gb = *(const float2*)(gbase + (size_t)r1 * WW);

    float minv0[2] = {3.4e38f, 3.4e38f};
    float minv1[2] = {3.4e38f, 3.4e38f};

    const int rbase = r0 * SCOLS + (tx << 1);
    const unsigned int mb0 = smem_u32(mbars);

    if (interior) mbar_wait(mb0, 0);                     // rows [0,28): k=0
    sad_step<true, false>(sT, rbase, m0r, m1r, minv0, minv1);

    if (interior) mbar_wait(mb0 + 8, 0);                 // rows [0,44): k=1..4
#pragma unroll 1
    for (int k = 1; k < 5; k++)
        sad_step<true, true>(sT, rbase + k * 4 * SCOLS, m0r, m1r, minv0, minv1);

    if (interior) mbar_wait(mb0 + 16, 0);                // full tile: k=5..9
#pragma unroll 1
    for (int k = 5; k < 9; k++)
        sad_step<true, true>(sT, rbase + k * 4 * SCOLS, m0r, m1r, minv0, minv1);
    sad_step<false, true>(sT, rbase + 9 * 4 * SCOLS, m0r, m1r, minv0, minv1);

    // ---- mask + reduction ----
    const float mn  = __uint_as_float(g_minbits);
    const float mx  = __uint_as_float(g_maxbits);
    const float thr = mn + (mx - mn) * (10.0f / 255.0f);

    float lsum = 0.f;
    int   lcnt = 0;
    if (ga.x > thr) { lsum += minv0[0]; lcnt++; }
    if (ga.y > thr) { lsum += minv0[1]; lcnt++; }
    if (gb.x > thr) { lsum += minv1[0]; lcnt++; }
    if (gb.y > thr) { lsum += minv1[1]; lcnt++; }

#pragma unroll
    for (int o = 16; o; o >>= 1) {
        lsum += __shfl_xor_sync(0xffffffffu, lsum, o);
        lcnt += __shfl_xor_sync(0xffffffffu, lcnt, o);
    }
    __shared__ float wsum[16];
    __shared__ int   wcnt[16];
    int lane = tid & 31, wid = tid >> 5;
    if (!lane) { wsum[wid] = lsum; wcnt[wid] = lcnt; }
    __syncthreads();
    if (tid == 0) {
        double bs = 0.0; long long bc = 0;
#pragma unroll
        for (int i = 0; i < 16; i++) { bs += (double)wsum[i]; bc += wcnt[i]; }
        atomicAdd(&g_sum, bs);
        atomicAdd(&g_cnt, (unsigned long long)bc);
    }
}

__global__ void fin_k(float* out) {
    unsigned long long c = g_cnt;
    out[0] = (c > 0ull) ? (float)(g_sum / (double)c) : 0.0f;
}

extern "C" void kernel_launch(void* const* d_in, const int* in_sizes, int n_in,
                              void* d_out, int out_size) {
    const float* ms  = (const float*)d_in[0];
    const float* tgt = (const float*)d_in[1];
    const float* mso = (const float*)d_in[2];
    const float* pan = (const float*)d_in[3];
    float* out = (float*)d_out;

    const int smem = CC * SCH * (int)sizeof(float);   // 196608 B
    cudaFuncSetAttribute(main_k, cudaFuncAttributeMaxDynamicSharedMemorySize, smem);

    init_k<<<1, 1>>>();
    mask_k<<<(NN * HH * WW) / 4 / 256, 256>>>(mso, pan);
    dim3 grid(WW / TW, HH / TH, NN), blk(32, 16);
    main_k<<<grid, blk, smem>>>(ms, tgt);
    fin_k<<<1, 1>>>(out);
}

// round 15
// speedup vs baseline: 1.7358x; 1.0128x over previous
#include <cuda_runtime.h>

#define HH 1024
#define WW 1024
#define CC 8
#define NN 2
#define TH 32
#define TW 64
#define SROWS 64                 // TH + 32
#define SCOLS 96                 // TW + 32
#define SCH (SROWS*SCOLS)
#define NTHR 512

// ---- device-global scratch / accumulators ----
__device__ __align__(16) float g_scratch[NN*HH*WW];   // gray = |mean_c(mso) - pan|
__device__ __align__(16) float g_msl[NN*HH*WW];       // per-pixel min shift loss
__device__ unsigned int g_minbits;
__device__ unsigned int g_maxbits;
__device__ double g_sum;
__device__ unsigned long long g_cnt;
__device__ unsigned int g_done;

__global__ void init_k() {
    g_minbits = 0x7F800000u;
    g_maxbits = 0u;
    g_sum = 0.0;
    g_cnt = 0ull;
    g_done = 0u;
}

__device__ __forceinline__ unsigned int smem_u32(const void* p) {
    unsigned int a;
    asm("{ .reg .u64 t; cvta.to.shared.u64 t, %1; cvt.u32.u64 %0, t; }"
        : "=r"(a) : "l"(p));
    return a;
}
__device__ __forceinline__ void mbar_init(unsigned int mbar, unsigned int cnt) {
    asm volatile("mbarrier.init.shared.b64 [%0], %1;" :: "r"(mbar), "r"(cnt) : "memory");
}
__device__ __forceinline__ void mbar_expect(unsigned int mbar, unsigned int bytes) {
    asm volatile("mbarrier.arrive.expect_tx.shared.b64 _, [%0], %1;"
                 :: "r"(mbar), "r"(bytes) : "memory");
}
__device__ __forceinline__ void bulk_cp(unsigned int dst, const void* src,
                                        unsigned int bytes, unsigned int mbar) {
    asm volatile("cp.async.bulk.shared::cta.global.mbarrier::complete_tx::bytes "
                 "[%0], [%1], %2, [%3];"
                 :: "r"(dst), "l"(src), "r"(bytes), "r"(mbar) : "memory");
}
__device__ __forceinline__ void mbar_wait(unsigned int mbar, unsigned int parity) {
    asm volatile(
        "{\n\t.reg .pred P;\n\t"
        "W%=:\n\t"
        "mbarrier.try_wait.parity.acquire.cta.shared::cta.b64 P, [%0], %1, 0x989680;\n\t"
        "@P bra.uni D%=;\n\t"
        "bra.uni W%=;\n\t"
        "D%=:\n\t}"
        :: "r"(mbar), "r"(parity) : "memory");
}

// One sliding-window step: target row (r0 + 4k) feeds px-row0 @ di=k and px-row1 @ di=k-1.
template<bool DO0, bool DO1>
__device__ __forceinline__ void sad_step(const float* __restrict__ sT, int rb,
                                         const float2* __restrict__ m0r,
                                         const float2* __restrict__ m1r,
                                         float* __restrict__ minv0,
                                         float* __restrict__ minv1) {
    float part0[18], part1[18];
#pragma unroll
    for (int c = 0; c < CC; c++) {
        const float* p = sT + c * SCH + rb;
        const float2 m0 = m0r[c];
        const float2 m1 = m1r[c];
#pragma unroll
        for (int dj = 0; dj < 9; dj++) {
            float2 tv = *(const float2*)(p + (dj << 2));
            if (DO0) {
                float dx = fabsf(m0.x - tv.x);
                float dy = fabsf(m0.y - tv.y);
                if (c == 0) { part0[dj*2+0] = dx; part0[dj*2+1] = dy; }
                else        { part0[dj*2+0] += dx; part0[dj*2+1] += dy; }
            }
            if (DO1) {
                float dx = fabsf(m1.x - tv.x);
                float dy = fabsf(m1.y - tv.y);
                if (c == 0) { part1[dj*2+0] = dx; part1[dj*2+1] = dy; }
                else        { part1[dj*2+0] += dx; part1[dj*2+1] += dy; }
            }
        }
    }
    if (DO0) {
#pragma unroll
        for (int dj = 0; dj < 9; dj++) {
            minv0[0] = fminf(minv0[0], part0[dj*2+0]);
            minv0[1] = fminf(minv0[1], part0[dj*2+1]);
        }
    }
    if (DO1) {
#pragma unroll
        for (int dj = 0; dj < 9; dj++) {
            minv1[0] = fminf(minv1[0], part1[dj*2+0]);
            minv1[1] = fminf(minv1[1], part1[dj*2+1]);
        }
    }
}

// Main pass: min-shift SAD + gray computation fused. 512 threads, 2 rows x 2 px/thread.
__global__ void __launch_bounds__(NTHR, 1) main_k(const float* __restrict__ ms,
                                                  const float* __restrict__ tgt,
                                                  const float* __restrict__ mso,
                                                  const float* __restrict__ pan) {
    extern __shared__ float sT[];   // [CC][SROWS][SCOLS]
    __shared__ __align__(8) unsigned long long mbars[3];
    __shared__ float smn[16], smx[16];

    const int n  = blockIdx.z;
    const int h0 = blockIdx.y * TH;
    const int w0 = blockIdx.x * TW;
    const int tx = threadIdx.x;      // 0..31 -> 2 px along w
    const int ty = threadIdx.y;      // 0..15 -> rows r0 and r0+4
    const int tid = ty * 32 + tx;

    const bool interior = (blockIdx.x > 0) && (blockIdx.x < gridDim.x - 1);

    if (interior) {
        // ---- async bulk-copy tile load: one 384B row per thread, 3 chunks ----
        if (tid == 0) {
            unsigned int mb = smem_u32(mbars);
            mbar_init(mb,      1);
            mbar_init(mb +  8, 1);
            mbar_init(mb + 16, 1);
        }
        __syncthreads();
        if (tid == 0) {
            unsigned int mb = smem_u32(mbars);
            mbar_expect(mb,      28 * CC * SCOLS * 4);   // rows [0,28)
            mbar_expect(mb +  8, 16 * CC * SCOLS * 4);   // rows [28,44)
            mbar_expect(mb + 16, 20 * CC * SCOLS * 4);   // rows [44,64)
        }
        {
            const int c = tid >> 6;          // 0..7
            const int r = tid & 63;          // 0..63
            int gr = h0 + r - 16;
            gr = gr < 0 ? -gr : (gr >= HH ? 2 * HH - 2 - gr : gr);
            const float* src = tgt + (((size_t)n * CC + c) * HH + gr) * WW + (w0 - 16);
            unsigned int dst = smem_u32(sT + (c * SROWS + r) * SCOLS);
            unsigned int mb  = smem_u32(mbars) + ((r < 28) ? 0u : (r < 44) ? 8u : 16u);
            bulk_cp(dst, src, SCOLS * 4, mb);
        }
    } else {
        // ---- manual loader with column reflect (boundary blocks) ----
        const int CPL4 = SCOLS / 4;
        const int NV4  = CC * SROWS * CPL4;
#pragma unroll 4
        for (int it = 0; it < NV4 / NTHR; it++) {
            int e4  = it * NTHR + tid;
            int c   = e4 / (SROWS * CPL4);
            int rem = e4 - c * (SROWS * CPL4);
            int r   = rem / CPL4;
            int q   = rem - r * CPL4;
            int gr = h0 + r - 16;
            gr = gr < 0 ? -gr : (gr >= HH ? 2 * HH - 2 - gr : gr);
            const float* src = tgt + (((size_t)n * CC + c) * HH + gr) * WW;
            int gcb = w0 + q * 4 - 16;
            float4 v;
            if (gcb >= 0 && gcb + 4 <= WW) {
                v = *(const float4*)(src + gcb);
            } else {
                int g0 = gcb, g1 = gcb + 1, g2 = gcb + 2, g3 = gcb + 3;
                g0 = g0 < 0 ? -g0 : (g0 >= WW ? 2 * WW - 2 - g0 : g0);
                g1 = g1 < 0 ? -g1 : (g1 >= WW ? 2 * WW - 2 - g1 : g1);
                g2 = g2 < 0 ? -g2 : (g2 >= WW ? 2 * WW - 2 - g2 : g2);
                g3 = g3 < 0 ? -g3 : (g3 >= WW ? 2 * WW - 2 - g3 : g3);
                v = make_float4(src[g0], src[g1], src[g2], src[g3]);
            }
            *(float4*)&sT[c * SCH + r * SCOLS + q * 4] = v;
        }
    }

    // rows owned by this thread: r0 and r0+4 (disjoint cover of 0..31)
    const int r0    = (ty & 3) + ((ty >> 2) << 3);
    const int r1    = r0 + 4;
    const int wbase = w0 + (tx << 1);
    const size_t pix0 = ((size_t)n << 20) + (size_t)(h0 + r0) * WW + wbase;
    const size_t pix1 = ((size_t)n << 20) + (size_t)(h0 + r1) * WW + wbase;

    // ms pixels (overlaps the async tile transfer)
    float2 m0r[CC], m1r[CC];
#pragma unroll
    for (int c = 0; c < CC; c++) {
        const float* base = &ms[(((size_t)n * CC + c) * HH + h0) * WW + wbase];
        m0r[c] = *(const float2*)(base + (size_t)r0 * WW);
        m1r[c] = *(const float2*)(base + (size_t)r1 * WW);
    }

    // ---- fused gray computation (was mask_k) — also overlaps the transfer ----
    {
        float2 a0 = make_float2(0.f, 0.f), a1 = make_float2(0.f, 0.f);
#pragma unroll
        for (int c = 0; c < CC; c++) {
            const float* base = &mso[(((size_t)n * CC + c) * HH + h0) * WW + wbase];
            float2 v0 = *(const float2*)(base + (size_t)r0 * WW);
            float2 v1 = *(const float2*)(base + (size_t)r1 * WW);
            a0.x += v0.x; a0.y += v0.y;
            a1.x += v1.x; a1.y += v1.y;
        }
        float2 p0 = *(const float2*)&pan[pix0];
        float2 p1 = *(const float2*)&pan[pix1];
        float2 gr0, gr1;
        gr0.x = fabsf(a0.x * 0.125f - p0.x);
        gr0.y = fabsf(a0.y * 0.125f - p0.y);
        gr1.x = fabsf(a1.x * 0.125f - p1.x);
        gr1.y = fabsf(a1.y * 0.125f - p1.y);
        *(float2*)&g_scratch[pix0] = gr0;
        *(float2*)&g_scratch[pix1] = gr1;

        float lmin = fminf(fminf(gr0.x, gr0.y), fminf(gr1.x, gr1.y));
        float lmax = fmaxf(fmaxf(gr0.x, gr0.y), fmaxf(gr1.x, gr1.y));
#pragma unroll
        for (int o = 16; o; o >>= 1) {
            lmin = fminf(lmin, __shfl_xor_sync(0xffffffffu, lmin, o));
            lmax = fmaxf(lmax, __shfl_xor_sync(0xffffffffu, lmax, o));
        }
        int lane = tid & 31, wid = tid >> 5;
        if (!lane) { smn[wid] = lmin; smx[wid] = lmax; }
        __syncthreads();   // also orders boundary-path sT writes before compute
        if (tid == 0) {
            float mn = smn[0], mx = smx[0];
#pragma unroll
            for (int i = 1; i < 16; i++) { mn = fminf(mn, smn[i]); mx = fmaxf(mx, smx[i]); }
            atomicMin(&g_minbits, __float_as_uint(mn));
            atomicMax(&g_maxbits, __float_as_uint(mx));
        }
    }

    float minv0[2] = {3.4e38f, 3.4e38f};
    float minv1[2] = {3.4e38f, 3.4e38f};

    const int rbase = r0 * SCOLS + (tx << 1);
    const unsigned int mb0 = smem_u32(mbars);

    if (interior) mbar_wait(mb0, 0);                     // rows [0,28): k=0
    sad_step<true, false>(sT, rbase, m0r, m1r, minv0, minv1);

    if (interior) mbar_wait(mb0 + 8, 0);                 // rows [0,44): k=1..4
#pragma unroll 1
    for (int k = 1; k < 5; k++)
        sad_step<true, true>(sT, rbase + k * 4 * SCOLS, m0r, m1r, minv0, minv1);

    if (interior) mbar_wait(mb0 + 16, 0);                // full tile: k=5..9
#pragma unroll 1
    for (int k = 5; k < 9; k++)
        sad_step<true, true>(sT, rbase + k * 4 * SCOLS, m0r, m1r, minv0, minv1);
    sad_step<false, true>(sT, rbase + 9 * 4 * SCOLS, m0r, m1r, minv0, minv1);

    // ---- store per-pixel min shift loss ----
    *(float2*)&g_msl[pix0] = make_float2(minv0[0], minv0[1]);
    *(float2*)&g_msl[pix1] = make_float2(minv1[0], minv1[1]);
}

// Final pass: threshold + masked mean; last block writes the scalar output.
__global__ void __launch_bounds__(512) reduce_k(float* __restrict__ out) {
    const int t = blockIdx.x * 512 + threadIdx.x;
    const int p = t << 2;

    const float mn  = __uint_as_float(g_minbits);
    const float mx  = __uint_as_float(g_maxbits);
    const float thr = mn + (mx - mn) * (10.0f / 255.0f);

    float4 g = *(const float4*)&g_scratch[p];
    float4 m = *(const float4*)&g_msl[p];

    float lsum = 0.f;
    int   lcnt = 0;
    if (g.x > thr) { lsum += m.x; lcnt++; }
    if (g.y > thr) { lsum += m.y; lcnt++; }
    if (g.z > thr) { lsum += m.z; lcnt++; }
    if (g.w > thr) { lsum += m.w; lcnt++; }

#pragma unroll
    for (int o = 16; o; o >>= 1) {
        lsum += __shfl_xor_sync(0xffffffffu, lsum, o);
        lcnt += __shfl_xor_sync(0xffffffffu, lcnt, o);
    }
    __shared__ float wsum[16];
    __shared__ int   wcnt[16];
    int lane = threadIdx.x & 31, wid = threadIdx.x >> 5;
    if (!lane) { wsum[wid] = lsum; wcnt[wid] = lcnt; }
    __syncthreads();
    if (threadIdx.x == 0) {
        double bs = 0.0; long long bc = 0;
#pragma unroll
        for (int i = 0; i < 16; i++) { bs += (double)wsum[i]; bc += wcnt[i]; }
        atomicAdd(&g_sum, bs);
        atomicAdd(&g_cnt, (unsigned long long)bc);
        __threadfence();
        unsigned int old = atomicAdd(&g_done, 1u);
        if (old == gridDim.x - 1) {
            __threadfence();
            unsigned long long c = g_cnt;
            out[0] = (c > 0ull) ? (float)(g_sum / (double)c) : 0.0f;
        }
    }
}

extern "C" void kernel_launch(void* const* d_in, const int* in_sizes, int n_in,
                              void* d_out, int out_size) {
    const float* ms  = (const float*)d_in[0];
    const float* tgt = (const float*)d_in[1];
    const float* mso = (const float*)d_in[2];
    const float* pan = (const float*)d_in[3];
    float* out = (float*)d_out;

    const int smem = CC * SCH * (int)sizeof(float);   // 196608 B
    cudaFuncSetAttribute(main_k, cudaFuncAttributeMaxDynamicSharedMemorySize, smem);

    init_k<<<1, 1>>>();
    dim3 grid(WW / TW, HH / TH, NN), blk(32, 16);
    main_k<<<grid, blk, smem>>>(ms, tgt, mso, pan);
    reduce_k<<<(NN * HH * WW) / 4 / 512, 512>>>(out);
}